// round 12
// baseline (speedup 1.0000x reference)
#include <cuda_runtime.h>
#include <cuda_bf16.h>
#include <cstdint>
#include <math.h>

#define NN   20000
#define EE   320000
#define DD   256
#define HH   8
#define LLAY 2
#define HUSZ 1024

// ================= scratch (static device arrays; no cudaMalloc) =================
__device__ float g_h   [NN * DD];
__device__ float g_qkv [NN * 768];
__device__ float g_agg [NN * DD];
__device__ int   g_cnt[NN];
__device__ int   g_rowptr[NN + 1];
__device__ int   g_cur[NN];
__device__ int   g_srcs[EE];
// bf16 triple-split buffers: act = [hi | lo | hi], wt = [hi | hi | lo]
__device__ __nv_bfloat16 g_a2[(size_t)NN * 3 * DD];
__device__ __nv_bfloat16 g_a3[(size_t)NN * 3 * HUSZ];
__device__ __nv_bfloat16 g_wt[3145728];

#define WT_QKVO(l, t) ((size_t)((l) * 4 + (t)) * 196608)  // [256][768]
#define WT_W1         ((size_t)1572864)                   // [1024][768]
#define WT_W2         ((size_t)2359296)                   // [256][3072]

__device__ __forceinline__ uint32_t smem_u32(const void* p) {
    uint32_t a;
    asm("{ .reg .u64 t; cvta.to.shared.u64 t, %1; cvt.u32.u64 %0, t; }" : "=r"(a) : "l"(p));
    return a;
}
__device__ __forceinline__ void ldmatrix_x4(uint32_t* r, uint32_t addr) {
    asm volatile("ldmatrix.sync.aligned.m8n8.x4.shared.b16 {%0,%1,%2,%3}, [%4];"
                 : "=r"(r[0]), "=r"(r[1]), "=r"(r[2]), "=r"(r[3]) : "r"(addr));
}
__device__ __forceinline__ void mma_bf16(float* c, const uint32_t* a, uint32_t b0, uint32_t b1) {
    asm volatile(
        "mma.sync.aligned.m16n8k16.row.col.f32.bf16.bf16.f32 "
        "{%0,%1,%2,%3}, {%4,%5,%6,%7}, {%8,%9}, {%0,%1,%2,%3};"
        : "+f"(c[0]), "+f"(c[1]), "+f"(c[2]), "+f"(c[3])
        : "r"(a[0]), "r"(a[1]), "r"(a[2]), "r"(a[3]), "r"(b0), "r"(b1));
}
__device__ __forceinline__ void cp_async16(uint32_t dst, const void* src, int sz) {
    asm volatile("cp.async.cg.shared.global [%0], [%1], 16, %2;"
                 :: "r"(dst), "l"(src), "r"(sz));
}
#define CP_COMMIT() asm volatile("cp.async.commit_group;" ::: "memory")
#define CP_WAIT1()  asm volatile("cp.async.wait_group 1;" ::: "memory")

#define LDK 40
#define ROWB (LDK * 2)                       // 80 bytes per smem row

// ============ 128x128 HMMA GEMM (QKV, W1) ============
#define STAGE_BYTES (2 * 128 * ROWB)         // 20480
#define GEMM_SMEM (3 * STAGE_BYTES)          // 61440
__global__ void __launch_bounds__(256)
gemm_mma_kernel(const __nv_bfloat16* __restrict__ A, const __nv_bfloat16* __restrict__ B,
                const float* __restrict__ bias, float* __restrict__ C,
                __nv_bfloat16* __restrict__ Y,
                int M, int N, int K2, int outK, int flags) {
    extern __shared__ __align__(16) char smem[];
    const uint32_t sbase = smem_u32(smem);

    const int tid = threadIdx.x;
    const int wid = tid >> 5, lane = tid & 31;
    const int warp_m = wid & 1;
    const int warp_n = wid >> 1;
    const int row0 = blockIdx.y * 128;
    const int col0 = blockIdx.x * 128;

    const int lseg = tid & 3;
    const int lrow = tid >> 2;

    float acc[4][4][4];
#pragma unroll
    for (int i = 0; i < 4; i++)
#pragma unroll
        for (int j = 0; j < 4; j++)
#pragma unroll
            for (int t = 0; t < 4; t++) acc[i][j][t] = 0.f;

    const int nchunks = K2 >> 5;

    const int a_mrow = warp_m * 64 + (lane & 15);
    const int a_kseg = (lane >> 4);
    const int b_nrow = warp_n * 32 + (lane & 7) + ((lane >> 4) << 3);
    const int b_kseg = (lane >> 3) & 1;

    const int gr0 = row0 + lrow, gr1 = row0 + lrow + 64;
    const int p0 = (gr0 < M) ? 16 : 0;
    const int p1 = (gr1 < M) ? 16 : 0;
    const __nv_bfloat16* aG0 = A + (size_t)gr0 * K2 + lseg * 8;
    const __nv_bfloat16* aG1 = A + (size_t)gr1 * K2 + lseg * 8;
    const __nv_bfloat16* bG0 = B + (size_t)(col0 + lrow) * K2 + lseg * 8;
    const __nv_bfloat16* bG1 = B + (size_t)(col0 + lrow + 64) * K2 + lseg * 8;
    const uint32_t sA0 = lrow * ROWB + lseg * 16;
    const uint32_t sA1 = (lrow + 64) * ROWB + lseg * 16;

#define ISSUE_LOAD(c)                                                          \
    do {                                                                       \
        if ((c) < nchunks) {                                                   \
            const int kb = (c) * 32;                                           \
            const uint32_t st = sbase + ((c) % 3) * STAGE_BYTES;               \
            cp_async16(st + sA0, aG0 + kb, p0);                                \
            cp_async16(st + sA1, aG1 + kb, p1);                                \
            cp_async16(st + 10240 + sA0, bG0 + kb, 16);                        \
            cp_async16(st + 10240 + sA1, bG1 + kb, 16);                        \
        }                                                                      \
        CP_COMMIT();                                                           \
    } while (0)

    ISSUE_LOAD(0);
    ISSUE_LOAD(1);

    for (int c = 0; c < nchunks; c++) {
        CP_WAIT1();
        __syncthreads();
        const uint32_t st = sbase + (c % 3) * STAGE_BYTES;
#pragma unroll
        for (int kst = 0; kst < 2; kst++) {
            const int k0 = kst * 16;
            uint32_t afr[4][4];
#pragma unroll
            for (int mf = 0; mf < 4; mf++) {
                uint32_t addr = st + (a_mrow + mf * 16) * ROWB + (k0 + a_kseg * 8) * 2;
                ldmatrix_x4(afr[mf], addr);
            }
            uint32_t bfr[2][4];
#pragma unroll
            for (int bp = 0; bp < 2; bp++) {
                uint32_t addr = st + 10240 + (b_nrow + bp * 16) * ROWB + (k0 + b_kseg * 8) * 2;
                ldmatrix_x4(bfr[bp], addr);
            }
#pragma unroll
            for (int mf = 0; mf < 4; mf++)
#pragma unroll
                for (int nf = 0; nf < 4; nf++) {
                    const int bp = nf >> 1, j = nf & 1;
                    mma_bf16(acc[mf][nf], afr[mf], bfr[bp][j * 2], bfr[bp][j * 2 + 1]);
                }
        }
        ISSUE_LOAD(c + 2);
    }
#undef ISSUE_LOAD

    const int mrow_lo = row0 + warp_m * 64 + (lane >> 2);
    const int ccol0   = col0 + warp_n * 32 + (lane & 3) * 2;
#pragma unroll
    for (int mf = 0; mf < 4; mf++) {
#pragma unroll
        for (int nf = 0; nf < 4; nf++) {
            int cc = ccol0 + nf * 8;
            float2 v0 = make_float2(acc[mf][nf][0], acc[mf][nf][1]);
            float2 v1 = make_float2(acc[mf][nf][2], acc[mf][nf][3]);
            if (flags & 1) {
                float b0 = bias[cc], b1 = bias[cc + 1];
                v0.x += b0; v0.y += b1; v1.x += b0; v1.y += b1;
            }
            if (flags & 2) {
                v0.x = fmaxf(v0.x, 0.f); v0.y = fmaxf(v0.y, 0.f);
                v1.x = fmaxf(v1.x, 0.f); v1.y = fmaxf(v1.y, 0.f);
            }
            int r0 = mrow_lo + mf * 16;
            int r1 = r0 + 8;
            if (flags & 4) {
#pragma unroll
                for (int h = 0; h < 2; h++) {
                    int r = h ? r1 : r0;
                    float2 v = h ? v1 : v0;
                    if (r >= M) continue;
                    __nv_bfloat16 h0 = __float2bfloat16(v.x);
                    __nv_bfloat16 h1 = __float2bfloat16(v.y);
                    __nv_bfloat16 l0 = __float2bfloat16(v.x - __bfloat162float(h0));
                    __nv_bfloat16 l1 = __float2bfloat16(v.y - __bfloat162float(h1));
                    __nv_bfloat16* yp = Y + (size_t)r * 3 * outK + cc;
                    *reinterpret_cast<__nv_bfloat162*>(yp)            = __halves2bfloat162(h0, h1);
                    *reinterpret_cast<__nv_bfloat162*>(yp + outK)     = __halves2bfloat162(l0, l1);
                    *reinterpret_cast<__nv_bfloat162*>(yp + 2 * outK) = __halves2bfloat162(h0, h1);
                }
            } else {
                if (r0 < M) *reinterpret_cast<float2*>(&C[(size_t)r0 * N + cc]) = v0;
                if (r1 < M) *reinterpret_cast<float2*>(&C[(size_t)r1 * N + cc]) = v1;
            }
        }
    }
}

// ============ 64x128 HMMA GEMM (Wo, W2 — fixes wave quantization at N=256) ============
// 8 warps (2m x 4n), warp tile 32x32, BK=32, 3-stage cp.async.
#define STAGE64 ((64 + 128) * ROWB)          // 15360
#define GEMM64_SMEM (3 * STAGE64)            // 46080
__global__ void __launch_bounds__(256)
gemm_mma64_kernel(const __nv_bfloat16* __restrict__ A, const __nv_bfloat16* __restrict__ B,
                  const float* __restrict__ bias, float* __restrict__ C,
                  int M, int N, int K2, int flags /*1=bias*/) {
    extern __shared__ __align__(16) char smem[];
    const uint32_t sbase = smem_u32(smem);

    const int tid = threadIdx.x;
    const int wid = tid >> 5, lane = tid & 31;
    const int warp_m = wid & 1;            // 0..1 (32 rows)
    const int warp_n = wid >> 1;           // 0..3 (32 cols)
    const int row0 = blockIdx.y * 64;
    const int col0 = blockIdx.x * 128;

    const int lseg = tid & 3;
    const int lrow = tid >> 2;             // 0..63

    float acc[2][4][4];
#pragma unroll
    for (int i = 0; i < 2; i++)
#pragma unroll
        for (int j = 0; j < 4; j++)
#pragma unroll
            for (int t = 0; t < 4; t++) acc[i][j][t] = 0.f;

    const int nchunks = K2 >> 5;

    const int a_mrow = warp_m * 32 + (lane & 15);
    const int a_kseg = (lane >> 4);
    const int b_nrow = warp_n * 32 + (lane & 7) + ((lane >> 4) << 3);
    const int b_kseg = (lane >> 3) & 1;

    const int gr0 = row0 + lrow;
    const int p0 = (gr0 < M) ? 16 : 0;
    const __nv_bfloat16* aG0 = A + (size_t)gr0 * K2 + lseg * 8;
    const __nv_bfloat16* bG0 = B + (size_t)(col0 + lrow) * K2 + lseg * 8;
    const __nv_bfloat16* bG1 = B + (size_t)(col0 + lrow + 64) * K2 + lseg * 8;
    const uint32_t sA0 = lrow * ROWB + lseg * 16;               // A: rows 0..63
    const uint32_t sB0 = 5120 + lrow * ROWB + lseg * 16;        // B: rows 0..63
    const uint32_t sB1 = 5120 + (lrow + 64) * ROWB + lseg * 16; // B: rows 64..127

#define ISSUE_LOAD64(c)                                                        \
    do {                                                                       \
        if ((c) < nchunks) {                                                   \
            const int kb = (c) * 32;                                           \
            const uint32_t st = sbase + ((c) % 3) * STAGE64;                   \
            cp_async16(st + sA0, aG0 + kb, p0);                                \
            cp_async16(st + sB0, bG0 + kb, 16);                                \
            cp_async16(st + sB1, bG1 + kb, 16);                                \
        }                                                                      \
        CP_COMMIT();                                                           \
    } while (0)

    ISSUE_LOAD64(0);
    ISSUE_LOAD64(1);

    for (int c = 0; c < nchunks; c++) {
        CP_WAIT1();
        __syncthreads();
        const uint32_t st = sbase + (c % 3) * STAGE64;
#pragma unroll
        for (int kst = 0; kst < 2; kst++) {
            const int k0 = kst * 16;
            uint32_t afr[2][4];
#pragma unroll
            for (int mf = 0; mf < 2; mf++) {
                uint32_t addr = st + (a_mrow + mf * 16) * ROWB + (k0 + a_kseg * 8) * 2;
                ldmatrix_x4(afr[mf], addr);
            }
            uint32_t bfr[2][4];
#pragma unroll
            for (int bp = 0; bp < 2; bp++) {
                uint32_t addr = st + 5120 + (b_nrow + bp * 16) * ROWB + (k0 + b_kseg * 8) * 2;
                ldmatrix_x4(bfr[bp], addr);
            }
#pragma unroll
            for (int mf = 0; mf < 2; mf++)
#pragma unroll
                for (int nf = 0; nf < 4; nf++) {
                    const int bp = nf >> 1, j = nf & 1;
                    mma_bf16(acc[mf][nf], afr[mf], bfr[bp][j * 2], bfr[bp][j * 2 + 1]);
                }
        }
        ISSUE_LOAD64(c + 2);
    }
#undef ISSUE_LOAD64

    const int mrow_lo = row0 + warp_m * 32 + (lane >> 2);
    const int ccol0   = col0 + warp_n * 32 + (lane & 3) * 2;
#pragma unroll
    for (int mf = 0; mf < 2; mf++) {
#pragma unroll
        for (int nf = 0; nf < 4; nf++) {
            int cc = ccol0 + nf * 8;
            float2 v0 = make_float2(acc[mf][nf][0], acc[mf][nf][1]);
            float2 v1 = make_float2(acc[mf][nf][2], acc[mf][nf][3]);
            if (flags & 1) {
                float b0 = bias[cc], b1 = bias[cc + 1];
                v0.x += b0; v0.y += b1; v1.x += b0; v1.y += b1;
            }
            int r0 = mrow_lo + mf * 16;
            int r1 = r0 + 8;
            if (r0 < M) *reinterpret_cast<float2*>(&C[(size_t)r0 * N + cc]) = v0;
            if (r1 < M) *reinterpret_cast<float2*>(&C[(size_t)r1 * N + cc]) = v1;
        }
    }
}

// ================= input copy + split + cnt zero (fused) =================
__global__ void copy_split_kernel(const float* __restrict__ X, float* __restrict__ Hout,
                                  __nv_bfloat16* __restrict__ Y, int* __restrict__ cnt) {
    int idx = blockIdx.x * blockDim.x + threadIdx.x;
    if (idx < NN) cnt[idx] = 0;
    if (idx >= NN * DD) return;
    float x = X[idx];
    Hout[idx] = x;
    int m = idx >> 8, k = idx & 255;
    __nv_bfloat16 hi = __float2bfloat16(x);
    __nv_bfloat16 lo = __float2bfloat16(x - __bfloat162float(hi));
    size_t base = (size_t)m * 768 + k;
    Y[base]       = hi;
    Y[base + 256] = lo;
    Y[base + 512] = hi;
}

// ================= all-weights split (one launch) =================
__global__ void split_wt_all_kernel(const float* __restrict__ Wq, const float* __restrict__ Wk,
                                    const float* __restrict__ Wv, const float* __restrict__ Wo,
                                    const float* __restrict__ w1, const float* __restrict__ w2,
                                    __nv_bfloat16* __restrict__ Y) {
    int idx = blockIdx.x * blockDim.x + threadIdx.x;
    if (idx >= 1048576) return;
    const float* src;
    int k, n, K;
    size_t dstbase;
    if (idx < 524288) {
        int w = idx >> 16, local = idx & 65535;
        int l = w >> 2, t = w & 3;
        const float* ws = (t == 0) ? Wq : (t == 1) ? Wk : (t == 2) ? Wv : Wo;
        src = ws + (size_t)l * 65536;
        k = local >> 8; n = local & 255; K = 256;
        dstbase = WT_QKVO(l, t);
    } else if (idx < 786432) {
        int local = idx - 524288;
        src = w1;
        k = local >> 10; n = local & 1023; K = 256;
        dstbase = WT_W1;
    } else {
        int local = idx - 786432;
        src = w2;
        k = local >> 8; n = local & 255; K = 1024;
        dstbase = WT_W2;
    }
    int Ncols = (dstbase == WT_W1) ? 1024 : 256;
    float x = src[(size_t)k * Ncols + n];
    __nv_bfloat16 hi = __float2bfloat16(x);
    __nv_bfloat16 lo = __float2bfloat16(x - __bfloat162float(hi));
    __nv_bfloat16* yp = Y + dstbase + (size_t)n * 3 * K;
    yp[k]         = hi;
    yp[K + k]     = hi;
    yp[2 * K + k] = lo;
}

// ================= CSR build =================
__global__ void hist_kernel(const int* __restrict__ dst, int* __restrict__ cnt, int e) {
    int i = blockIdx.x * blockDim.x + threadIdx.x;
    if (i < e) atomicAdd(&cnt[dst[i]], 1);
}
__global__ void scan_kernel(const int* __restrict__ cnt, int* __restrict__ rowptr,
                            int* __restrict__ cur, int n) {
    __shared__ int sh[1024];
    const int PER = 20;
    int tid = threadIdx.x;
    int base = tid * PER;
    int loc[PER];
    int run = 0;
#pragma unroll
    for (int i = 0; i < PER; i++) {
        int v = (base + i < n) ? cnt[base + i] : 0;
        run += v;
        loc[i] = run;
    }
    sh[tid] = run;
    __syncthreads();
    for (int off = 1; off < 1024; off <<= 1) {
        int v = 0;
        if (tid >= off) v = sh[tid - off];
        __syncthreads();
        sh[tid] += v;
        __syncthreads();
    }
    int offset = (tid > 0) ? sh[tid - 1] : 0;
    if (tid == 0) rowptr[0] = 0;
#pragma unroll
    for (int i = 0; i < PER; i++)
        if (base + i < n) {
            int excl = offset + (i > 0 ? loc[i - 1] : 0);
            rowptr[base + i + 1] = offset + loc[i];
            cur[base + i] = excl;
        }
}
__global__ void scatter_kernel(const int* __restrict__ src, const int* __restrict__ dst,
                               int* __restrict__ cur, int* __restrict__ srcs, int e) {
    int i = blockIdx.x * blockDim.x + threadIdx.x;
    if (i < e) {
        int p = atomicAdd(&cur[dst[i]], 1);
        srcs[p] = src[i];
    }
}
__global__ void sortseg_kernel(const int* __restrict__ rowptr, int* __restrict__ srcs, int n) {
    int node = blockIdx.x * blockDim.x + threadIdx.x;
    if (node >= n) return;
    int beg = rowptr[node], end = rowptr[node + 1];
    for (int i = beg + 1; i < end; i++) {
        int key = srcs[i];
        int j = i - 1;
        while (j >= beg && srcs[j] > key) { srcs[j + 1] = srcs[j]; j--; }
        srcs[j + 1] = key;
    }
}

// ===== edge attention: one warp per (node,head); unroll-2 paired reductions =====
__global__ void __launch_bounds__(256)
edge_attn_kernel(const float* __restrict__ QKV, const int* __restrict__ rowptr,
                 const int* __restrict__ srcs, __nv_bfloat16* __restrict__ Y) {
    int node = blockIdx.x;
    int w    = threadIdx.x >> 5;
    int lane = threadIdx.x & 31;
    int off  = w * 32 + lane;
    int beg = rowptr[node], end = rowptr[node + 1];
    float qv = QKV[(size_t)node * 768 + off];
    float m = -INFINITY, z = 0.f, acc = 0.f;
    const float rscale = 0.17677669529663687f;

    int e = beg;
    for (; e + 2 <= end; e += 2) {
        int s0 = srcs[e], s1 = srcs[e + 1];
        const float* r0 = QKV + (size_t)s0 * 768 + off;
        const float* r1 = QKV + (size_t)s1 * 768 + off;
        float kv0 = r0[256], vv0 = r0[512];
        float kv1 = r1[256], vv1 = r1[512];
        float q0 = qv * kv0, q1 = qv * kv1;
#pragma unroll
        for (int o = 16; o; o >>= 1) {
            q0 += __shfl_xor_sync(0xffffffffu, q0, o);
            q1 += __shfl_xor_sync(0xffffffffu, q1, o);
        }
        float l0 = q0 * rscale, l1 = q1 * rscale;
        float mn = fmaxf(m, l0);
        float sc = expf(m - mn);
        float ea = expf(l0 - mn);
        z = z * sc + ea; acc = acc * sc + ea * vv0; m = mn;
        mn = fmaxf(m, l1);
        sc = expf(m - mn);
        ea = expf(l1 - mn);
        z = z * sc + ea; acc = acc * sc + ea * vv1; m = mn;
    }
    if (e < end) {
        int s = srcs[e];
        const float* r = QKV + (size_t)s * 768 + off;
        float kv = r[256], vv = r[512];
        float q0 = qv * kv;
#pragma unroll
        for (int o = 16; o; o >>= 1) q0 += __shfl_xor_sync(0xffffffffu, q0, o);
        float l = q0 * rscale;
        float mn = fmaxf(m, l);
        float sc = expf(m - mn);
        float ea = expf(l - mn);
        z = z * sc + ea; acc = acc * sc + ea * vv; m = mn;
    }
    float res = acc / (z + 1e-9f);
    __nv_bfloat16 hi = __float2bfloat16(res);
    __nv_bfloat16 lo = __float2bfloat16(res - __bfloat162float(hi));
    size_t base = (size_t)node * 768 + off;
    Y[base]       = hi;
    Y[base + 256] = lo;
    Y[base + 512] = hi;
}

// ================= residual + layernorm; writes h fp32 + bf16 splits =================
__global__ void __launch_bounds__(256)
resid_ln_kernel(const float* __restrict__ attn_out, float* __restrict__ h,
                const float* __restrict__ gain, const float* __restrict__ beta,
                __nv_bfloat16* __restrict__ Y, int n) {
    int row = blockIdx.x * 8 + (threadIdx.x >> 5);
    if (row >= n) return;
    int lane = threadIdx.x & 31;
    float x[8];
    float s = 0.f;
#pragma unroll
    for (int i = 0; i < 8; i++) {
        int c = lane + i * 32;
        x[i] = attn_out[row * DD + c] + h[row * DD + c];
        s += x[i];
    }
#pragma unroll
    for (int o = 16; o; o >>= 1) s += __shfl_xor_sync(0xffffffffu, s, o);
    float mu = s * (1.f / DD);
    float vs = 0.f;
#pragma unroll
    for (int i = 0; i < 8; i++) { float d = x[i] - mu; vs = fmaf(d, d, vs); }
#pragma unroll
    for (int o = 16; o; o >>= 1) vs += __shfl_xor_sync(0xffffffffu, vs, o);
    float r = rsqrtf(vs * (1.f / DD) + 1e-5f);
#pragma unroll
    for (int i = 0; i < 8; i++) {
        int c = lane + i * 32;
        float val = (x[i] - mu) * r * gain[c] + beta[c];
        h[row * DD + c] = val;
        __nv_bfloat16 hi = __float2bfloat16(val);
        __nv_bfloat16 lo = __float2bfloat16(val - __bfloat162float(hi));
        size_t base = (size_t)row * 768 + c;
        Y[base]       = hi;
        Y[base + 256] = lo;
        Y[base + 512] = hi;
    }
}

// ================= launch =================
extern "C" void kernel_launch(void* const* d_in, const int* in_sizes, int n_in,
                              void* d_out, int out_size) {
    const float* in_h  = (const float*)d_in[0];
    const int*   src   = (const int*)  d_in[1];
    const int*   dst   = (const int*)  d_in[2];
    const float* Wq    = (const float*)d_in[3];
    const float* Wk    = (const float*)d_in[4];
    const float* Wv    = (const float*)d_in[5];
    const float* Wo    = (const float*)d_in[6];
    const float* ln_g  = (const float*)d_in[7];
    const float* ln_b  = (const float*)d_in[8];
    const float* w1    = (const float*)d_in[9];
    const float* b1    = (const float*)d_in[10];
    const float* w2    = (const float*)d_in[11];
    const float* b2    = (const float*)d_in[12];
    float* out = (float*)d_out;

    void *p_h, *p_qkv, *p_agg, *p_cnt, *p_rowptr, *p_cur, *p_srcs, *p_a2, *p_a3, *p_wt;
    cudaGetSymbolAddress(&p_h,   g_h);
    cudaGetSymbolAddress(&p_qkv, g_qkv);
    cudaGetSymbolAddress(&p_agg, g_agg);
    cudaGetSymbolAddress(&p_cnt, g_cnt);
    cudaGetSymbolAddress(&p_rowptr, g_rowptr);
    cudaGetSymbolAddress(&p_cur, g_cur);
    cudaGetSymbolAddress(&p_srcs, g_srcs);
    cudaGetSymbolAddress(&p_a2,  g_a2);
    cudaGetSymbolAddress(&p_a3,  g_a3);
    cudaGetSymbolAddress(&p_wt,  g_wt);
    float* hbuf   = (float*)p_h;
    float* qkvb   = (float*)p_qkv;
    float* aggb   = (float*)p_agg;
    int* cnt      = (int*)p_cnt;
    int* rowptr   = (int*)p_rowptr;
    int* cur      = (int*)p_cur;
    int* srcs     = (int*)p_srcs;
    __nv_bfloat16* a2 = (__nv_bfloat16*)p_a2;
    __nv_bfloat16* a3 = (__nv_bfloat16*)p_a3;
    __nv_bfloat16* wt = (__nv_bfloat16*)p_wt;

    cudaFuncSetAttribute(gemm_mma_kernel, cudaFuncAttributeMaxDynamicSharedMemorySize,
                         GEMM_SMEM);
    cudaFuncSetAttribute(gemm_mma64_kernel, cudaFuncAttributeMaxDynamicSharedMemorySize,
                         GEMM64_SMEM);

    const int mtiles  = (NN + 127) / 128;
    const int mtiles64 = (NN + 63) / 64;
    dim3 gQKV(6, mtiles);       // N=768, 128-tile
    dim3 gW1(8, mtiles);        // N=1024, 128-tile
    dim3 gN256_64(2, mtiles64); // N=256, 64-tile

    // 1: input copy + split + cnt zero
    copy_split_kernel<<<(NN * DD + 255) / 256, 256>>>(in_h, hbuf, a2, cnt);
    // 2: all weights split
    split_wt_all_kernel<<<4096, 256>>>(Wq, Wk, Wv, Wo, w1, w2, wt);
    // 3: histogram
    hist_kernel<<<(EE + 255) / 256, 256>>>(dst, cnt, EE);
    // 4: first QKV GEMM  (profiled launch)
    gemm_mma_kernel<<<gQKV, 256, GEMM_SMEM>>>(a2, wt + WT_QKVO(0, 0), nullptr, qkvb, nullptr,
                                              NN, 768, 768, 0, 0);
    // 5-7: CSR completion
    scan_kernel<<<1, 1024>>>(cnt, rowptr, cur, NN);
    scatter_kernel<<<(EE + 255) / 256, 256>>>(src, dst, cur, srcs, EE);
    sortseg_kernel<<<(NN + 127) / 128, 128>>>(rowptr, srcs, NN);

    for (int l = 0; l < LLAY; l++) {
        if (l > 0)
            gemm_mma_kernel<<<gQKV, 256, GEMM_SMEM>>>(a2, wt + WT_QKVO(l, 0), nullptr, qkvb,
                                                      nullptr, NN, 768, 768, 0, 0);
        edge_attn_kernel<<<NN, 256>>>(qkvb, rowptr, srcs, a2);
        gemm_mma64_kernel<<<gN256_64, 256, GEMM64_SMEM>>>(a2, wt + WT_QKVO(l, 3), nullptr,
                                                          aggb, NN, DD, 768, 0);
        resid_ln_kernel<<<(NN + 7) / 8, 256>>>(aggb, hbuf, ln_g + (size_t)l * DD,
                                               ln_b + (size_t)l * DD, a2, NN);
    }

    // FFN
    gemm_mma_kernel<<<gW1, 256, GEMM_SMEM>>>(a2, wt + WT_W1, b1, nullptr, a3,
                                             NN, HUSZ, 768, HUSZ, 1 | 2 | 4);
    gemm_mma64_kernel<<<gN256_64, 256, GEMM64_SMEM>>>(a3, wt + WT_W2, b2, out,
                                                      NN, DD, 3 * HUSZ, 1);
}

// round 16
// speedup vs baseline: 1.1706x; 1.1706x over previous
#include <cuda_runtime.h>
#include <cuda_bf16.h>
#include <cstdint>
#include <math.h>

#define NN   20000
#define EE   320000
#define DD   256
#define HH   8
#define LLAY 2
#define HUSZ 1024

// ================= scratch (static device arrays; no cudaMalloc) =================
__device__ float g_h   [NN * DD];
__device__ float g_qkv [NN * 768];
__device__ float g_agg [NN * DD];
__device__ int   g_cnt[NN];
__device__ int   g_rowptr[NN + 1];
__device__ int   g_cur[NN];
__device__ int   g_srcs[EE];
// bf16 triple-split buffers: act = [hi | lo | hi], wt = [hi | hi | lo]
__device__ __nv_bfloat16 g_a2[(size_t)NN * 3 * DD];
__device__ __nv_bfloat16 g_a3[(size_t)NN * 3 * HUSZ];
__device__ __nv_bfloat16 g_wt[3145728];

#define WT_QKVO(l, t) ((size_t)((l) * 4 + (t)) * 196608)  // [256][768]
#define WT_W1         ((size_t)1572864)                   // [1024][768]
#define WT_W2         ((size_t)2359296)                   // [256][3072]

__device__ __forceinline__ uint32_t smem_u32(const void* p) {
    uint32_t a;
    asm("{ .reg .u64 t; cvta.to.shared.u64 t, %1; cvt.u32.u64 %0, t; }" : "=r"(a) : "l"(p));
    return a;
}
__device__ __forceinline__ void ldmatrix_x4(uint32_t* r, uint32_t addr) {
    asm volatile("ldmatrix.sync.aligned.m8n8.x4.shared.b16 {%0,%1,%2,%3}, [%4];"
                 : "=r"(r[0]), "=r"(r[1]), "=r"(r[2]), "=r"(r[3]) : "r"(addr));
}
__device__ __forceinline__ void mma_bf16(float* c, const uint32_t* a, uint32_t b0, uint32_t b1) {
    asm volatile(
        "mma.sync.aligned.m16n8k16.row.col.f32.bf16.bf16.f32 "
        "{%0,%1,%2,%3}, {%4,%5,%6,%7}, {%8,%9}, {%0,%1,%2,%3};"
        : "+f"(c[0]), "+f"(c[1]), "+f"(c[2]), "+f"(c[3])
        : "r"(a[0]), "r"(a[1]), "r"(a[2]), "r"(a[3]), "r"(b0), "r"(b1));
}
__device__ __forceinline__ void cp_async16(uint32_t dst, const void* src, int sz) {
    asm volatile("cp.async.cg.shared.global [%0], [%1], 16, %2;"
                 :: "r"(dst), "l"(src), "r"(sz));
}
#define CP_COMMIT() asm volatile("cp.async.commit_group;" ::: "memory")
#define CP_WAIT1()  asm volatile("cp.async.wait_group 1;" ::: "memory")

#define LDK 40
#define ROWB (LDK * 2)                       // 80 bytes per smem row

// ============ 128x128 HMMA GEMM (QKV, W1) ============
#define STAGE_BYTES (2 * 128 * ROWB)         // 20480
#define GEMM_SMEM (3 * STAGE_BYTES)          // 61440
__global__ void __launch_bounds__(256)
gemm_mma_kernel(const __nv_bfloat16* __restrict__ A, const __nv_bfloat16* __restrict__ B,
                const float* __restrict__ bias, float* __restrict__ C,
                __nv_bfloat16* __restrict__ Y,
                int M, int N, int K2, int outK, int flags) {
    extern __shared__ __align__(16) char smem[];
    const uint32_t sbase = smem_u32(smem);

    const int tid = threadIdx.x;
    const int wid = tid >> 5, lane = tid & 31;
    const int warp_m = wid & 1;
    const int warp_n = wid >> 1;
    const int row0 = blockIdx.y * 128;
    const int col0 = blockIdx.x * 128;

    const int lseg = tid & 3;
    const int lrow = tid >> 2;

    float acc[4][4][4];
#pragma unroll
    for (int i = 0; i < 4; i++)
#pragma unroll
        for (int j = 0; j < 4; j++)
#pragma unroll
            for (int t = 0; t < 4; t++) acc[i][j][t] = 0.f;

    const int nchunks = K2 >> 5;

    const int a_mrow = warp_m * 64 + (lane & 15);
    const int a_kseg = (lane >> 4);
    const int b_nrow = warp_n * 32 + (lane & 7) + ((lane >> 4) << 3);
    const int b_kseg = (lane >> 3) & 1;

    const int gr0 = row0 + lrow, gr1 = row0 + lrow + 64;
    const int p0 = (gr0 < M) ? 16 : 0;
    const int p1 = (gr1 < M) ? 16 : 0;
    const __nv_bfloat16* aG0 = A + (size_t)gr0 * K2 + lseg * 8;
    const __nv_bfloat16* aG1 = A + (size_t)gr1 * K2 + lseg * 8;
    const __nv_bfloat16* bG0 = B + (size_t)(col0 + lrow) * K2 + lseg * 8;
    const __nv_bfloat16* bG1 = B + (size_t)(col0 + lrow + 64) * K2 + lseg * 8;
    const uint32_t sA0 = lrow * ROWB + lseg * 16;
    const uint32_t sA1 = (lrow + 64) * ROWB + lseg * 16;

#define ISSUE_LOAD(c)                                                          \
    do {                                                                       \
        if ((c) < nchunks) {                                                   \
            const int kb = (c) * 32;                                           \
            const uint32_t st = sbase + ((c) % 3) * STAGE_BYTES;               \
            cp_async16(st + sA0, aG0 + kb, p0);                                \
            cp_async16(st + sA1, aG1 + kb, p1);                                \
            cp_async16(st + 10240 + sA0, bG0 + kb, 16);                        \
            cp_async16(st + 10240 + sA1, bG1 + kb, 16);                        \
        }                                                                      \
        CP_COMMIT();                                                           \
    } while (0)

    ISSUE_LOAD(0);
    ISSUE_LOAD(1);

    for (int c = 0; c < nchunks; c++) {
        CP_WAIT1();
        __syncthreads();
        const uint32_t st = sbase + (c % 3) * STAGE_BYTES;
#pragma unroll
        for (int kst = 0; kst < 2; kst++) {
            const int k0 = kst * 16;
            uint32_t afr[4][4];
#pragma unroll
            for (int mf = 0; mf < 4; mf++) {
                uint32_t addr = st + (a_mrow + mf * 16) * ROWB + (k0 + a_kseg * 8) * 2;
                ldmatrix_x4(afr[mf], addr);
            }
            uint32_t bfr[2][4];
#pragma unroll
            for (int bp = 0; bp < 2; bp++) {
                uint32_t addr = st + 10240 + (b_nrow + bp * 16) * ROWB + (k0 + b_kseg * 8) * 2;
                ldmatrix_x4(bfr[bp], addr);
            }
#pragma unroll
            for (int mf = 0; mf < 4; mf++)
#pragma unroll
                for (int nf = 0; nf < 4; nf++) {
                    const int bp = nf >> 1, j = nf & 1;
                    mma_bf16(acc[mf][nf], afr[mf], bfr[bp][j * 2], bfr[bp][j * 2 + 1]);
                }
        }
        ISSUE_LOAD(c + 2);
    }
#undef ISSUE_LOAD

    const int mrow_lo = row0 + warp_m * 64 + (lane >> 2);
    const int ccol0   = col0 + warp_n * 32 + (lane & 3) * 2;
#pragma unroll
    for (int mf = 0; mf < 4; mf++) {
#pragma unroll
        for (int nf = 0; nf < 4; nf++) {
            int cc = ccol0 + nf * 8;
            float2 v0 = make_float2(acc[mf][nf][0], acc[mf][nf][1]);
            float2 v1 = make_float2(acc[mf][nf][2], acc[mf][nf][3]);
            if (flags & 1) {
                float b0 = bias[cc], b1 = bias[cc + 1];
                v0.x += b0; v0.y += b1; v1.x += b0; v1.y += b1;
            }
            if (flags & 2) {
                v0.x = fmaxf(v0.x, 0.f); v0.y = fmaxf(v0.y, 0.f);
                v1.x = fmaxf(v1.x, 0.f); v1.y = fmaxf(v1.y, 0.f);
            }
            int r0 = mrow_lo + mf * 16;
            int r1 = r0 + 8;
            if (flags & 4) {
#pragma unroll
                for (int h = 0; h < 2; h++) {
                    int r = h ? r1 : r0;
                    float2 v = h ? v1 : v0;
                    if (r >= M) continue;
                    __nv_bfloat16 h0 = __float2bfloat16(v.x);
                    __nv_bfloat16 h1 = __float2bfloat16(v.y);
                    __nv_bfloat16 l0 = __float2bfloat16(v.x - __bfloat162float(h0));
                    __nv_bfloat16 l1 = __float2bfloat16(v.y - __bfloat162float(h1));
                    __nv_bfloat16* yp = Y + (size_t)r * 3 * outK + cc;
                    *reinterpret_cast<__nv_bfloat162*>(yp)            = __halves2bfloat162(h0, h1);
                    *reinterpret_cast<__nv_bfloat162*>(yp + outK)     = __halves2bfloat162(l0, l1);
                    *reinterpret_cast<__nv_bfloat162*>(yp + 2 * outK) = __halves2bfloat162(h0, h1);
                }
            } else {
                if (r0 < M) *reinterpret_cast<float2*>(&C[(size_t)r0 * N + cc]) = v0;
                if (r1 < M) *reinterpret_cast<float2*>(&C[(size_t)r1 * N + cc]) = v1;
            }
        }
    }
}

// ============ 64x128 HMMA GEMM (Wo, W2) ============
#define STAGE64 ((64 + 128) * ROWB)          // 15360
#define GEMM64_SMEM (3 * STAGE64)            // 46080
__global__ void __launch_bounds__(256)
gemm_mma64_kernel(const __nv_bfloat16* __restrict__ A, const __nv_bfloat16* __restrict__ B,
                  const float* __restrict__ bias, float* __restrict__ C,
                  int M, int N, int K2, int flags /*1=bias*/) {
    extern __shared__ __align__(16) char smem[];
    const uint32_t sbase = smem_u32(smem);

    const int tid = threadIdx.x;
    const int wid = tid >> 5, lane = tid & 31;
    const int warp_m = wid & 1;
    const int warp_n = wid >> 1;
    const int row0 = blockIdx.y * 64;
    const int col0 = blockIdx.x * 128;

    const int lseg = tid & 3;
    const int lrow = tid >> 2;

    float acc[2][4][4];
#pragma unroll
    for (int i = 0; i < 2; i++)
#pragma unroll
        for (int j = 0; j < 4; j++)
#pragma unroll
            for (int t = 0; t < 4; t++) acc[i][j][t] = 0.f;

    const int nchunks = K2 >> 5;

    const int a_mrow = warp_m * 32 + (lane & 15);
    const int a_kseg = (lane >> 4);
    const int b_nrow = warp_n * 32 + (lane & 7) + ((lane >> 4) << 3);
    const int b_kseg = (lane >> 3) & 1;

    const int gr0 = row0 + lrow;
    const int p0 = (gr0 < M) ? 16 : 0;
    const __nv_bfloat16* aG0 = A + (size_t)gr0 * K2 + lseg * 8;
    const __nv_bfloat16* bG0 = B + (size_t)(col0 + lrow) * K2 + lseg * 8;
    const __nv_bfloat16* bG1 = B + (size_t)(col0 + lrow + 64) * K2 + lseg * 8;
    const uint32_t sA0 = lrow * ROWB + lseg * 16;
    const uint32_t sB0 = 5120 + lrow * ROWB + lseg * 16;
    const uint32_t sB1 = 5120 + (lrow + 64) * ROWB + lseg * 16;

#define ISSUE_LOAD64(c)                                                        \
    do {                                                                       \
        if ((c) < nchunks) {                                                   \
            const int kb = (c) * 32;                                           \
            const uint32_t st = sbase + ((c) % 3) * STAGE64;                   \
            cp_async16(st + sA0, aG0 + kb, p0);                                \
            cp_async16(st + sB0, bG0 + kb, 16);                                \
            cp_async16(st + sB1, bG1 + kb, 16);                                \
        }                                                                      \
        CP_COMMIT();                                                           \
    } while (0)

    ISSUE_LOAD64(0);
    ISSUE_LOAD64(1);

    for (int c = 0; c < nchunks; c++) {
        CP_WAIT1();
        __syncthreads();
        const uint32_t st = sbase + (c % 3) * STAGE64;
#pragma unroll
        for (int kst = 0; kst < 2; kst++) {
            const int k0 = kst * 16;
            uint32_t afr[2][4];
#pragma unroll
            for (int mf = 0; mf < 2; mf++) {
                uint32_t addr = st + (a_mrow + mf * 16) * ROWB + (k0 + a_kseg * 8) * 2;
                ldmatrix_x4(afr[mf], addr);
            }
            uint32_t bfr[2][4];
#pragma unroll
            for (int bp = 0; bp < 2; bp++) {
                uint32_t addr = st + 5120 + (b_nrow + bp * 16) * ROWB + (k0 + b_kseg * 8) * 2;
                ldmatrix_x4(bfr[bp], addr);
            }
#pragma unroll
            for (int mf = 0; mf < 2; mf++)
#pragma unroll
                for (int nf = 0; nf < 4; nf++) {
                    const int bp = nf >> 1, j = nf & 1;
                    mma_bf16(acc[mf][nf], afr[mf], bfr[bp][j * 2], bfr[bp][j * 2 + 1]);
                }
        }
        ISSUE_LOAD64(c + 2);
    }
#undef ISSUE_LOAD64

    const int mrow_lo = row0 + warp_m * 32 + (lane >> 2);
    const int ccol0   = col0 + warp_n * 32 + (lane & 3) * 2;
#pragma unroll
    for (int mf = 0; mf < 2; mf++) {
#pragma unroll
        for (int nf = 0; nf < 4; nf++) {
            int cc = ccol0 + nf * 8;
            float2 v0 = make_float2(acc[mf][nf][0], acc[mf][nf][1]);
            float2 v1 = make_float2(acc[mf][nf][2], acc[mf][nf][3]);
            if (flags & 1) {
                float b0 = bias[cc], b1 = bias[cc + 1];
                v0.x += b0; v0.y += b1; v1.x += b0; v1.y += b1;
            }
            int r0 = mrow_lo + mf * 16;
            int r1 = r0 + 8;
            if (r0 < M) *reinterpret_cast<float2*>(&C[(size_t)r0 * N + cc]) = v0;
            if (r1 < M) *reinterpret_cast<float2*>(&C[(size_t)r1 * N + cc]) = v1;
        }
    }
}

// ================= input copy + split + cnt zero (fused) =================
__global__ void copy_split_kernel(const float* __restrict__ X, float* __restrict__ Hout,
                                  __nv_bfloat16* __restrict__ Y, int* __restrict__ cnt) {
    int idx = blockIdx.x * blockDim.x + threadIdx.x;
    if (idx < NN) cnt[idx] = 0;
    if (idx >= NN * DD) return;
    float x = X[idx];
    Hout[idx] = x;
    int m = idx >> 8, k = idx & 255;
    __nv_bfloat16 hi = __float2bfloat16(x);
    __nv_bfloat16 lo = __float2bfloat16(x - __bfloat162float(hi));
    size_t base = (size_t)m * 768 + k;
    Y[base]       = hi;
    Y[base + 256] = lo;
    Y[base + 512] = hi;
}

// ================= all-weights split (one launch) =================
__global__ void split_wt_all_kernel(const float* __restrict__ Wq, const float* __restrict__ Wk,
                                    const float* __restrict__ Wv, const float* __restrict__ Wo,
                                    const float* __restrict__ w1, const float* __restrict__ w2,
                                    __nv_bfloat16* __restrict__ Y) {
    int idx = blockIdx.x * blockDim.x + threadIdx.x;
    if (idx >= 1048576) return;
    const float* src;
    int k, n, K;
    size_t dstbase;
    if (idx < 524288) {
        int w = idx >> 16, local = idx & 65535;
        int l = w >> 2, t = w & 3;
        const float* ws = (t == 0) ? Wq : (t == 1) ? Wk : (t == 2) ? Wv : Wo;
        src = ws + (size_t)l * 65536;
        k = local >> 8; n = local & 255; K = 256;
        dstbase = WT_QKVO(l, t);
    } else if (idx < 786432) {
        int local = idx - 524288;
        src = w1;
        k = local >> 10; n = local & 1023; K = 256;
        dstbase = WT_W1;
    } else {
        int local = idx - 786432;
        src = w2;
        k = local >> 8; n = local & 255; K = 1024;
        dstbase = WT_W2;
    }
    int Ncols = (dstbase == WT_W1) ? 1024 : 256;
    float x = src[(size_t)k * Ncols + n];
    __nv_bfloat16 hi = __float2bfloat16(x);
    __nv_bfloat16 lo = __float2bfloat16(x - __bfloat162float(hi));
    __nv_bfloat16* yp = Y + dstbase + (size_t)n * 3 * K;
    yp[k]         = hi;
    yp[K + k]     = hi;
    yp[2 * K + k] = lo;
}

// ================= CSR build =================
__global__ void hist_kernel(const int* __restrict__ dst, int* __restrict__ cnt, int e) {
    int i = blockIdx.x * blockDim.x + threadIdx.x;
    if (i < e) atomicAdd(&cnt[dst[i]], 1);
}
__global__ void scan_kernel(const int* __restrict__ cnt, int* __restrict__ rowptr,
                            int* __restrict__ cur, int n) {
    __shared__ int sh[1024];
    const int PER = 20;
    int tid = threadIdx.x;
    int base = tid * PER;
    int loc[PER];
    int run = 0;
#pragma unroll
    for (int i = 0; i < PER; i++) {
        int v = (base + i < n) ? cnt[base + i] : 0;
        run += v;
        loc[i] = run;
    }
    sh[tid] = run;
    __syncthreads();
    for (int off = 1; off < 1024; off <<= 1) {
        int v = 0;
        if (tid >= off) v = sh[tid - off];
        __syncthreads();
        sh[tid] += v;
        __syncthreads();
    }
    int offset = (tid > 0) ? sh[tid - 1] : 0;
    if (tid == 0) rowptr[0] = 0;
#pragma unroll
    for (int i = 0; i < PER; i++)
        if (base + i < n) {
            int excl = offset + (i > 0 ? loc[i - 1] : 0);
            rowptr[base + i + 1] = offset + loc[i];
            cur[base + i] = excl;
        }
}
__global__ void scatter_kernel(const int* __restrict__ src, const int* __restrict__ dst,
                               int* __restrict__ cur, int* __restrict__ srcs, int e) {
    int i = blockIdx.x * blockDim.x + threadIdx.x;
    if (i < e) {
        int p = atomicAdd(&cur[dst[i]], 1);
        srcs[p] = src[i];
    }
}
__global__ void sortseg_kernel(const int* __restrict__ rowptr, int* __restrict__ srcs, int n) {
    int node = blockIdx.x * blockDim.x + threadIdx.x;
    if (node >= n) return;
    int beg = rowptr[node], end = rowptr[node + 1];
    for (int i = beg + 1; i < end; i++) {
        int key = srcs[i];
        int j = i - 1;
        while (j >= beg && srcs[j] > key) { srcs[j + 1] = srcs[j]; j--; }
        srcs[j + 1] = key;
    }
}

// ===== edge attention: ONE WARP PER NODE, all 8 heads. Lane l owns dims [8l, 8l+8).
// Head h lives on lane group {4h..4h+3}; per-head dot = 8-fma + 2 shuffles.
__global__ void __launch_bounds__(256)
edge_attn_kernel(const float* __restrict__ QKV, const int* __restrict__ rowptr,
                 const int* __restrict__ srcs, __nv_bfloat16* __restrict__ Y) {
    int node = blockIdx.x * 8 + (threadIdx.x >> 5);
    if (node >= NN) return;
    int lane = threadIdx.x & 31;
    int c0 = lane * 8;

    const float4* qp = reinterpret_cast<const float4*>(QKV + (size_t)node * 768 + c0);
    float4 qa = qp[0], qb = qp[1];

    int beg = rowptr[node], end = rowptr[node + 1];
    float m = -INFINITY, z = 0.f;
    float acc[8] = {0.f, 0.f, 0.f, 0.f, 0.f, 0.f, 0.f, 0.f};
    const float rscale = 0.17677669529663687f;  // 1/sqrt(32)

    for (int e = beg; e < end; e++) {
        int s = srcs[e];
        const float* row = QKV + (size_t)s * 768 + c0;
        float4 ka = *reinterpret_cast<const float4*>(row + 256);
        float4 kb = *reinterpret_cast<const float4*>(row + 260);
        float4 va = *reinterpret_cast<const float4*>(row + 512);
        float4 vb = *reinterpret_cast<const float4*>(row + 516);
        float pa = qa.x * ka.x + qa.y * ka.y + qa.z * ka.z + qa.w * ka.w;
        float pb = qb.x * kb.x + qb.y * kb.y + qb.z * kb.z + qb.w * kb.w;
        float p = pa + pb;
        p += __shfl_xor_sync(0xffffffffu, p, 1);
        p += __shfl_xor_sync(0xffffffffu, p, 2);   // all 4 lanes of head group share sum
        float logit = p * rscale;
        float mn = fmaxf(m, logit);
        float sc = expf(m - mn);
        float ea = expf(logit - mn);
        z = z * sc + ea;
        acc[0] = acc[0] * sc + ea * va.x;
        acc[1] = acc[1] * sc + ea * va.y;
        acc[2] = acc[2] * sc + ea * va.z;
        acc[3] = acc[3] * sc + ea * va.w;
        acc[4] = acc[4] * sc + ea * vb.x;
        acc[5] = acc[5] * sc + ea * vb.y;
        acc[6] = acc[6] * sc + ea * vb.z;
        acc[7] = acc[7] * sc + ea * vb.w;
        m = mn;
    }

    float zd = z + 1e-9f;
    union { __nv_bfloat162 b2[4]; uint4 u; } H, L;
#pragma unroll
    for (int i = 0; i < 4; i++) {
        float r0 = acc[2 * i]     / zd;
        float r1 = acc[2 * i + 1] / zd;
        __nv_bfloat16 h0 = __float2bfloat16(r0);
        __nv_bfloat16 h1 = __float2bfloat16(r1);
        __nv_bfloat16 l0 = __float2bfloat16(r0 - __bfloat162float(h0));
        __nv_bfloat16 l1 = __float2bfloat16(r1 - __bfloat162float(h1));
        H.b2[i] = __halves2bfloat162(h0, h1);
        L.b2[i] = __halves2bfloat162(l0, l1);
    }
    __nv_bfloat16* yp = Y + (size_t)node * 768 + c0;
    *reinterpret_cast<uint4*>(yp)       = H.u;
    *reinterpret_cast<uint4*>(yp + 256) = L.u;
    *reinterpret_cast<uint4*>(yp + 512) = H.u;
}

// ================= residual + layernorm; writes h fp32 + bf16 splits =================
__global__ void __launch_bounds__(256)
resid_ln_kernel(const float* __restrict__ attn_out, float* __restrict__ h,
                const float* __restrict__ gain, const float* __restrict__ beta,
                __nv_bfloat16* __restrict__ Y, int n) {
    int row = blockIdx.x * 8 + (threadIdx.x >> 5);
    if (row >= n) return;
    int lane = threadIdx.x & 31;
    float x[8];
    float s = 0.f;
#pragma unroll
    for (int i = 0; i < 8; i++) {
        int c = lane + i * 32;
        x[i] = attn_out[row * DD + c] + h[row * DD + c];
        s += x[i];
    }
#pragma unroll
    for (int o = 16; o; o >>= 1) s += __shfl_xor_sync(0xffffffffu, s, o);
    float mu = s * (1.f / DD);
    float vs = 0.f;
#pragma unroll
    for (int i = 0; i < 8; i++) { float d = x[i] - mu; vs = fmaf(d, d, vs); }
#pragma unroll
    for (int o = 16; o; o >>= 1) vs += __shfl_xor_sync(0xffffffffu, vs, o);
    float r = rsqrtf(vs * (1.f / DD) + 1e-5f);
#pragma unroll
    for (int i = 0; i < 8; i++) {
        int c = lane + i * 32;
        float val = (x[i] - mu) * r * gain[c] + beta[c];
        h[row * DD + c] = val;
        __nv_bfloat16 hi = __float2bfloat16(val);
        __nv_bfloat16 lo = __float2bfloat16(val - __bfloat162float(hi));
        size_t base = (size_t)row * 768 + c;
        Y[base]       = hi;
        Y[base + 256] = lo;
        Y[base + 512] = hi;
    }
}

// ================= launch =================
extern "C" void kernel_launch(void* const* d_in, const int* in_sizes, int n_in,
                              void* d_out, int out_size) {
    const float* in_h  = (const float*)d_in[0];
    const int*   src   = (const int*)  d_in[1];
    const int*   dst   = (const int*)  d_in[2];
    const float* Wq    = (const float*)d_in[3];
    const float* Wk    = (const float*)d_in[4];
    const float* Wv    = (const float*)d_in[5];
    const float* Wo    = (const float*)d_in[6];
    const float* ln_g  = (const float*)d_in[7];
    const float* ln_b  = (const float*)d_in[8];
    const float* w1    = (const float*)d_in[9];
    const float* b1    = (const float*)d_in[10];
    const float* w2    = (const float*)d_in[11];
    const float* b2    = (const float*)d_in[12];
    float* out = (float*)d_out;

    void *p_h, *p_qkv, *p_agg, *p_cnt, *p_rowptr, *p_cur, *p_srcs, *p_a2, *p_a3, *p_wt;
    cudaGetSymbolAddress(&p_h,   g_h);
    cudaGetSymbolAddress(&p_qkv, g_qkv);
    cudaGetSymbolAddress(&p_agg, g_agg);
    cudaGetSymbolAddress(&p_cnt, g_cnt);
    cudaGetSymbolAddress(&p_rowptr, g_rowptr);
    cudaGetSymbolAddress(&p_cur, g_cur);
    cudaGetSymbolAddress(&p_srcs, g_srcs);
    cudaGetSymbolAddress(&p_a2,  g_a2);
    cudaGetSymbolAddress(&p_a3,  g_a3);
    cudaGetSymbolAddress(&p_wt,  g_wt);
    float* hbuf   = (float*)p_h;
    float* qkvb   = (float*)p_qkv;
    float* aggb   = (float*)p_agg;
    int* cnt      = (int*)p_cnt;
    int* rowptr   = (int*)p_rowptr;
    int* cur      = (int*)p_cur;
    int* srcs     = (int*)p_srcs;
    __nv_bfloat16* a2 = (__nv_bfloat16*)p_a2;
    __nv_bfloat16* a3 = (__nv_bfloat16*)p_a3;
    __nv_bfloat16* wt = (__nv_bfloat16*)p_wt;

    cudaFuncSetAttribute(gemm_mma_kernel, cudaFuncAttributeMaxDynamicSharedMemorySize,
                         GEMM_SMEM);
    cudaFuncSetAttribute(gemm_mma64_kernel, cudaFuncAttributeMaxDynamicSharedMemorySize,
                         GEMM64_SMEM);

    const int mtiles  = (NN + 127) / 128;
    const int mtiles64 = (NN + 63) / 64;
    dim3 gQKV(6, mtiles);       // N=768, 128-tile
    dim3 gW1(8, mtiles);        // N=1024, 128-tile
    dim3 gN256_64(2, mtiles64); // N=256, 64-tile

    // 1: input copy + split + cnt zero
    copy_split_kernel<<<(NN * DD + 255) / 256, 256>>>(in_h, hbuf, a2, cnt);
    // 2: all weights split
    split_wt_all_kernel<<<4096, 256>>>(Wq, Wk, Wv, Wo, w1, w2, wt);
    // 3: histogram
    hist_kernel<<<(EE + 255) / 256, 256>>>(dst, cnt, EE);
    // 4: first QKV GEMM  (profiled launch)
    gemm_mma_kernel<<<gQKV, 256, GEMM_SMEM>>>(a2, wt + WT_QKVO(0, 0), nullptr, qkvb, nullptr,
                                              NN, 768, 768, 0, 0);
    // 5-7: CSR completion
    scan_kernel<<<1, 1024>>>(cnt, rowptr, cur, NN);
    scatter_kernel<<<(EE + 255) / 256, 256>>>(src, dst, cur, srcs, EE);
    sortseg_kernel<<<(NN + 127) / 128, 128>>>(rowptr, srcs, NN);

    for (int l = 0; l < LLAY; l++) {
        if (l > 0)
            gemm_mma_kernel<<<gQKV, 256, GEMM_SMEM>>>(a2, wt + WT_QKVO(l, 0), nullptr, qkvb,
                                                      nullptr, NN, 768, 768, 0, 0);
        edge_attn_kernel<<<(NN + 7) / 8, 256>>>(qkvb, rowptr, srcs, a2);
        gemm_mma64_kernel<<<gN256_64, 256, GEMM64_SMEM>>>(a2, wt + WT_QKVO(l, 3), nullptr,
                                                          aggb, NN, DD, 768, 0);
        resid_ln_kernel<<<(NN + 7) / 8, 256>>>(aggb, hbuf, ln_g + (size_t)l * DD,
                                               ln_b + (size_t)l * DD, a2, NN);
    }

    // FFN
    gemm_mma_kernel<<<gW1, 256, GEMM_SMEM>>>(a2, wt + WT_W1, b1, nullptr, a3,
                                             NN, HUSZ, 768, HUSZ, 1 | 2 | 4);
    gemm_mma64_kernel<<<gN256_64, 256, GEMM64_SMEM>>>(a3, wt + WT_W2, b2, out,
                                                      NN, DD, 3 * HUSZ, 1);
}